// round 14
// baseline (speedup 1.0000x reference)
#include <cuda_runtime.h>
#include <math.h>

// Problem constants
#define B 16
#define L 2048
#define M 32000
#define MP1 32001
#define D 512

// Scratch (static __device__, allocation-free)
__device__ float g_inv_e[MP1];      // 1/max(||emb_w[t]||,1)
__device__ float g_cdot[MP1];       // raw dot(emb_w[M], emb_w[t])
__device__ float g_inv_p[L];        // 1/max(||pos_w[l]||,1)
__device__ float g_logits[B * L];   // masked-row logits, then probs (in place)
__device__ float g_sel[B * D];      // sel_output
__device__ float g_ip[B * M];       // inner products

// Packed f32x2 FMA (sm_10x): d = a*b + c elementwise on two packed floats.
__device__ __forceinline__ unsigned long long ffma2(unsigned long long a,
                                                    unsigned long long b,
                                                    unsigned long long c) {
    unsigned long long d;
    asm("fma.rn.f32x2 %0, %1, %2, %3;" : "=l"(d) : "l"(a), "l"(b), "l"(c));
    return d;
}

__device__ __forceinline__ float ull_lo(unsigned long long v) {
    float2 f; asm("mov.b64 {%0, %1}, %2;" : "=f"(f.x), "=f"(f.y) : "l"(v));
    return f.x + f.y;
}

// ---------------------------------------------------------------------------
// K1: row norms for emb_w (32001 rows) and pos_w (2048 rows), plus
//     cdot[t] = dot(emb_w[M], emb_w[t]) fused into the same emb_w read.
//     One warp per row.
// ---------------------------------------------------------------------------
__global__ __launch_bounds__(256) void k_norms(const float* __restrict__ emb,
                                               const float* __restrict__ pos) {
    int wid  = (blockIdx.x * blockDim.x + threadIdx.x) >> 5;
    int lane = threadIdx.x & 31;
    if (wid < MP1) {
        const float4* row = (const float4*)(emb + (size_t)wid * D);
        const float4* qm  = (const float4*)(emb + (size_t)M * D);
        float ss = 0.0f, dq = 0.0f;
#pragma unroll
        for (int i = 0; i < 4; i++) {
            float4 v = row[lane + 32 * i];
            float4 q = qm[lane + 32 * i];
            ss += v.x * v.x + v.y * v.y + v.z * v.z + v.w * v.w;
            dq += v.x * q.x + v.y * q.y + v.z * q.z + v.w * q.w;
        }
#pragma unroll
        for (int o = 16; o; o >>= 1) {
            ss += __shfl_xor_sync(0xffffffffu, ss, o);
            dq += __shfl_xor_sync(0xffffffffu, dq, o);
        }
        if (lane == 0) {
            g_inv_e[wid] = 1.0f / fmaxf(sqrtf(ss), 1.0f);
            g_cdot[wid]  = dq;
        }
    } else if (wid < MP1 + L) {
        int l = wid - MP1;
        const float4* row = (const float4*)(pos + (size_t)l * D);
        float ss = 0.0f;
#pragma unroll
        for (int i = 0; i < 4; i++) {
            float4 v = row[lane + 32 * i];
            ss += v.x * v.x + v.y * v.y + v.z * v.z + v.w * v.w;
        }
#pragma unroll
        for (int o = 16; o; o >>= 1) ss += __shfl_xor_sync(0xffffffffu, ss, o);
        if (lane == 0) g_inv_p[l] = 1.0f / fmaxf(sqrtf(ss), 1.0f);
    }
}

// ---------------------------------------------------------------------------
// K2: masked-row attention logits, ALL batches in one pass over pos_w.
// ---------------------------------------------------------------------------
__global__ __launch_bounds__(256) void k_logits(const float* __restrict__ pos,
                                                const int* __restrict__ x,
                                                const int* __restrict__ mask_idx) {
    __shared__ float s_pw[B][D];   // 32 KB
    __shared__ int   s_pidx[B];
    __shared__ float s_pinv[B];
    int tid = threadIdx.x;
    if (tid < B) {
        int p = mask_idx[tid];
        s_pidx[tid] = p;
        s_pinv[tid] = g_inv_p[p];
    }
    __syncthreads();
    for (int i = tid; i < B * D; i += 256) {
        int b = i >> 9, d = i & (D - 1);
        s_pw[b][d] = pos[(size_t)s_pidx[b] * D + d];
    }
    __syncthreads();

    int w = tid >> 5, lane = tid & 31;
    int m = blockIdx.x * 8 + w;

    const float4* prow = (const float4*)(pos + (size_t)m * D);
    float4 v[4];
#pragma unroll
    for (int i = 0; i < 4; i++) v[i] = prow[lane + 32 * i];
    float invm  = g_inv_p[m];
    float inv_eM = g_inv_e[M];

    float c_l = 0.0f;
    if (lane < B) {
        int t = (m == s_pidx[lane]) ? M : x[lane * L + m];
        c_l = g_cdot[t] * g_inv_e[t];
    }

#pragma unroll
    for (int b = 0; b < B; b++) {
        const float4* sp = (const float4*)s_pw[b];
        float pd = 0.0f;
#pragma unroll
        for (int i = 0; i < 4; i++) {
            float4 u = sp[lane + 32 * i];
            pd += v[i].x * u.x + v[i].y * u.y + v[i].z * u.z + v[i].w * u.w;
        }
#pragma unroll
        for (int o = 16; o; o >>= 1) pd += __shfl_xor_sync(0xffffffffu, pd, o);
        float cb = __shfl_sync(0xffffffffu, c_l, b);
        if (lane == 0)
            g_logits[b * L + m] = (cb * inv_eM + pd * invm * s_pinv[b]) * (1.0f / 32.0f);
    }
}

// ---------------------------------------------------------------------------
// K3: softmax over L per batch (in place), zero g_sel[b], zero out[0] (+tail).
// ---------------------------------------------------------------------------
__global__ __launch_bounds__(1024) void k_softmax(float* __restrict__ out, int out_size) {
    __shared__ float sred[32];
    int b = blockIdx.x, tid = threadIdx.x, lane = tid & 31, w = tid >> 5;
    float* lg = g_logits + b * L;
    float v0 = lg[tid], v1 = lg[tid + 1024];

    float mx = fmaxf(v0, v1);
#pragma unroll
    for (int o = 16; o; o >>= 1) mx = fmaxf(mx, __shfl_xor_sync(0xffffffffu, mx, o));
    if (lane == 0) sred[w] = mx;
    __syncthreads();
    if (w == 0) {
        float m2 = sred[lane];
#pragma unroll
        for (int o = 16; o; o >>= 1) m2 = fmaxf(m2, __shfl_xor_sync(0xffffffffu, m2, o));
        if (lane == 0) sred[0] = m2;
    }
    __syncthreads();
    mx = sred[0];

    float e0 = expf(v0 - mx), e1 = expf(v1 - mx);
    float s = e0 + e1;
#pragma unroll
    for (int o = 16; o; o >>= 1) s += __shfl_xor_sync(0xffffffffu, s, o);
    __syncthreads();
    if (lane == 0) sred[w] = s;
    __syncthreads();
    if (w == 0) {
        float s2 = sred[lane];
#pragma unroll
        for (int o = 16; o; o >>= 1) s2 += __shfl_xor_sync(0xffffffffu, s2, o);
        if (lane == 0) sred[0] = s2;
    }
    __syncthreads();
    float inv = 1.0f / sred[0];
    lg[tid] = e0 * inv;
    lg[tid + 1024] = e1 * inv;
    if (tid < D) g_sel[b * D + tid] = 0.0f;
    if (b == 0) {
        if (tid == 0) out[0] = 0.0f;                         // re-zeroed every replay
        for (int i = B * D + 1 + tid; i < out_size; i += 1024) out[i] = 0.0f;
    }
}

// ---------------------------------------------------------------------------
// K4: sel_output[b] = sum_m p[b][m] * inv_e[t] * emb_w[t].
//     grid (L/64, B), block 512: 4 m-subgroups x 128 column-threads.
// ---------------------------------------------------------------------------
__global__ __launch_bounds__(512) void k_selout(const float* __restrict__ emb,
                                                const int* __restrict__ x,
                                                const int* __restrict__ mask_idx) {
    __shared__ float  s_p[64];
    __shared__ int    s_t[64];
    __shared__ float4 s_acc[3][128];   // partials from subgroups 1..3
    int b = blockIdx.y, m0 = blockIdx.x * 64;
    int p = mask_idx[b];
    if (threadIdx.x < 64) {
        int m = m0 + threadIdx.x;
        int t = (m == p) ? M : x[b * L + m];
        s_t[threadIdx.x] = t;
        s_p[threadIdx.x] = g_logits[b * L + m] * g_inv_e[t];
    }
    __syncthreads();

    const float4* emb4 = (const float4*)emb;
    int c = threadIdx.x & 127;     // float4 column 0..127
    int s = threadIdx.x >> 7;      // subgroup 0..3 -> rows s*16 .. s*16+15
    float4 acc = make_float4(0.f, 0.f, 0.f, 0.f);
#pragma unroll
    for (int i = 0; i < 16; i++) {
        int   r = s_t[s * 16 + i];
        float w = s_p[s * 16 + i];
        float4 v = emb4[(size_t)r * (D / 4) + c];
        acc.x += w * v.x; acc.y += w * v.y; acc.z += w * v.z; acc.w += w * v.w;
    }
    if (s > 0) s_acc[s - 1][c] = acc;
    __syncthreads();
    if (s == 0) {
        float4 a1 = s_acc[0][c], a2 = s_acc[1][c], a3 = s_acc[2][c];
        acc.x += a1.x + a2.x + a3.x;
        acc.y += a1.y + a2.y + a3.y;
        acc.z += a1.z + a2.z + a3.z;
        acc.w += a1.w + a2.w + a3.w;
        float* dst = g_sel + b * D + c * 4;
        atomicAdd(dst + 0, acc.x);
        atomicAdd(dst + 1, acc.y);
        atomicAdd(dst + 2, acc.z);
        atomicAdd(dst + 3, acc.w);
    }
}

// ---------------------------------------------------------------------------
// K5: inner_prod[b][j] = (sel[b] . emb_w[j]) * inv_e[j] for j < M.
//     grid 500, block 256. J-tile=4 per warp: 4 emb rows register-resident as
//     NATIVE ulonglong2 (no unions -> no local-memory demotion), sel smem
//     chunk read once per b feeds all 4 dots (smem traffic /4). f32x2 FMA
//     halves the FFMA instruction count. Lanes 0..15 store 4 consecutive j
//     as one float4. Block 0 copies sel_output into out[1..B*D].
// ---------------------------------------------------------------------------
__global__ __launch_bounds__(256) void k_ip(const float* __restrict__ emb,
                                            float* __restrict__ out, int out_size) {
    __shared__ __align__(16) float s_sel[B * D];  // 32 KB
    for (int i = threadIdx.x; i < B * D; i += 256) s_sel[i] = g_sel[i];
    __syncthreads();

    if (blockIdx.x == 0) {
        int lim = out_size - 1; if (lim > B * D) lim = B * D;
        for (int i = threadIdx.x; i < lim; i += 256) out[1 + i] = s_sel[i];
    }

    int w    = threadIdx.x >> 5;
    int lane = threadIdx.x & 31;
    const ulonglong2* emb2 = (const ulonglong2*)emb;   // 16B granules; row = 128
    const ulonglong2* sel2 = (const ulonglong2*)s_sel;

#pragma unroll
    for (int g = 0; g < 2; g++) {
        int jbase = blockIdx.x * 64 + (w + 8 * g) * 4;   // 4 consecutive j

        // 4 emb rows, 64B per lane per row, native 64-bit packed registers
        ulonglong2 v0[4], v1[4], v2[4], v3[4];
#pragma unroll
        for (int i = 0; i < 4; i++) {
            v0[i] = emb2[(size_t)(jbase + 0) * 128 + lane + 32 * i];
            v1[i] = emb2[(size_t)(jbase + 1) * 128 + lane + 32 * i];
            v2[i] = emb2[(size_t)(jbase + 2) * 128 + lane + 32 * i];
            v3[i] = emb2[(size_t)(jbase + 3) * 128 + lane + 32 * i];
        }
        float inv0 = g_inv_e[jbase + 0];
        float inv1 = g_inv_e[jbase + 1];
        float inv2 = g_inv_e[jbase + 2];
        float inv3 = g_inv_e[jbase + 3];

        float keep0 = 0.f, keep1 = 0.f, keep2 = 0.f, keep3 = 0.f;
#pragma unroll
        for (int b = 0; b < B; b++) {
            unsigned long long a0 = 0ull, a1 = 0ull, a2 = 0ull, a3 = 0ull;
#pragma unroll
            for (int i = 0; i < 4; i++) {
                ulonglong2 u = sel2[b * 128 + lane + 32 * i];
                a0 = ffma2(v0[i].x, u.x, a0); a0 = ffma2(v0[i].y, u.y, a0);
                a1 = ffma2(v1[i].x, u.x, a1); a1 = ffma2(v1[i].y, u.y, a1);
                a2 = ffma2(v2[i].x, u.x, a2); a2 = ffma2(v2[i].y, u.y, a2);
                a3 = ffma2(v3[i].x, u.x, a3); a3 = ffma2(v3[i].y, u.y, a3);
            }
            float r0 = ull_lo(a0), r1 = ull_lo(a1);
            float r2 = ull_lo(a2), r3 = ull_lo(a3);
#pragma unroll
            for (int o = 16; o; o >>= 1) {
                r0 += __shfl_xor_sync(0xffffffffu, r0, o);
                r1 += __shfl_xor_sync(0xffffffffu, r1, o);
                r2 += __shfl_xor_sync(0xffffffffu, r2, o);
                r3 += __shfl_xor_sync(0xffffffffu, r3, o);
            }
            if (lane == b) {
                keep0 = r0 * inv0; keep1 = r1 * inv1;
                keep2 = r2 * inv2; keep3 = r3 * inv3;
            }
        }
        if (lane < B) {
            *(float4*)(g_ip + (size_t)lane * M + jbase) =
                make_float4(keep0, keep1, keep2, keep3);
        }
    }
}

// ---------------------------------------------------------------------------
// K6: per-batch log-softmax over M and NLL accumulation straight into out[0].
// ---------------------------------------------------------------------------
__global__ __launch_bounds__(1024) void k_loss(const int* __restrict__ x,
                                               const int* __restrict__ mask_idx,
                                               float* __restrict__ out) {
    __shared__ float sred[32];
    int b = blockIdx.x, tid = threadIdx.x, lane = tid & 31, w = tid >> 5;
    const float* ip = g_ip + b * M;

    float mx = -1e30f;
    for (int i = tid; i < M; i += 1024) mx = fmaxf(mx, ip[i]);
#pragma unroll
    for (int o = 16; o; o >>= 1) mx = fmaxf(mx, __shfl_xor_sync(0xffffffffu, mx, o));
    if (lane == 0) sred[w] = mx;
    __syncthreads();
    if (w == 0) {
        float m2 = sred[lane];
#pragma unroll
        for (int o = 16; o; o >>= 1) m2 = fmaxf(m2, __shfl_xor_sync(0xffffffffu, m2, o));
        if (lane == 0) sred[0] = m2;
    }
    __syncthreads();
    float bmx = sred[0];

    float s = 0.0f;
    for (int i = tid; i < M; i += 1024) s += expf(ip[i] - bmx);
#pragma unroll
    for (int o = 16; o; o >>= 1) s += __shfl_xor_sync(0xffffffffu, s, o);
    __syncthreads();
    if (lane == 0) sred[w] = s;
    __syncthreads();
    if (w == 0) {
        float s2 = sred[lane];
#pragma unroll
        for (int o = 16; o; o >>= 1) s2 += __shfl_xor_sync(0xffffffffu, s2, o);
        if (lane == 0) sred[0] = s2;
    }
    __syncthreads();
    if (tid == 0) {
        int t = x[b * L + mask_idx[b]];
        float logp = ip[t] - bmx - logf(sred[0]);
        atomicAdd(out, -logp * (1.0f / (float)B));
    }
}

// ---------------------------------------------------------------------------
extern "C" void kernel_launch(void* const* d_in, const int* in_sizes, int n_in,
                              void* d_out, int out_size) {
    const int*   x    = nullptr;
    const int*   midx = nullptr;
    const float* emb  = nullptr;
    const float* pos  = nullptr;
    for (int i = 0; i < n_in; i++) {
        switch (in_sizes[i]) {
            case B * L:     x    = (const int*)d_in[i];   break;
            case B:         midx = (const int*)d_in[i];   break;
            case MP1 * D:   emb  = (const float*)d_in[i]; break;
            case L * D:     pos  = (const float*)d_in[i]; break;
            default: break;
        }
    }
    float* out = (float*)d_out;

    // K1: norms + cdot (one warp per row, 34049 rows)
    {
        int warps = MP1 + L;
        int blocks = (warps + 7) / 8;
        k_norms<<<blocks, 256>>>(emb, pos);
    }
    // K2: masked-row logits, single pass over pos_w for all batches
    k_logits<<<L / 8, 256>>>(pos, x, midx);
    // K3: softmax per batch + zero sel + zero out[0]/tail
    k_softmax<<<B, 1024>>>(out, out_size);
    // K4: weighted gather sum -> sel_output (512 threads, smem-reduced)
    {
        dim3 grid(L / 64, B);
        k_selout<<<grid, 512>>>(emb, x, midx);
    }
    // K5: inner products vs full vocab (J-tile 4, native ull2, f32x2)
    k_ip<<<M / 64, 256>>>(emb, out, out_size);
    // K6: log-softmax + loss -> out[0]
    k_loss<<<B, 1024>>>(x, midx, out);
}

// round 17
// speedup vs baseline: 1.0752x; 1.0752x over previous
#include <cuda_runtime.h>
#include <math.h>

// Problem constants
#define B 16
#define L 2048
#define M 32000
#define MP1 32001
#define D 512

// Scratch (static __device__, allocation-free)
__device__ float g_inv_e[MP1];      // 1/max(||emb_w[t]||,1)
__device__ float g_cdot[MP1];       // raw dot(emb_w[M], emb_w[t])
__device__ float g_inv_p[L];        // 1/max(||pos_w[l]||,1)
__device__ float g_enum[B * L];     // exp(logit) (unnormalized probs)
__device__ float g_sum[B];          // per-batch sum of exp(logit)
__device__ float g_sel[B * D];      // sel_output
__device__ float g_ip[B * M];       // inner products

// ---------------------------------------------------------------------------
// K1: row norms for emb_w (32001 rows) and pos_w (2048 rows), plus
//     cdot[t] = dot(emb_w[M], emb_w[t]) fused into the same emb_w read.
//     One warp per row. Block 0 also zeroes all per-replay accumulators.
// ---------------------------------------------------------------------------
__global__ __launch_bounds__(256) void k_norms(const float* __restrict__ emb,
                                               const float* __restrict__ pos,
                                               float* __restrict__ out, int out_size) {
    if (blockIdx.x == 0) {
        int tid = threadIdx.x;
        if (tid == 0) out[0] = 0.0f;                          // re-zeroed every replay
        for (int i = tid; i < B; i += 256) g_sum[i] = 0.0f;
        for (int i = tid; i < B * D; i += 256) g_sel[i] = 0.0f;
        for (int i = B * D + 1 + tid; i < out_size; i += 256) out[i] = 0.0f;
    }
    int wid  = (blockIdx.x * blockDim.x + threadIdx.x) >> 5;
    int lane = threadIdx.x & 31;
    if (wid < MP1) {
        const float4* row = (const float4*)(emb + (size_t)wid * D);
        const float4* qm  = (const float4*)(emb + (size_t)M * D);
        float ss = 0.0f, dq = 0.0f;
#pragma unroll
        for (int i = 0; i < 4; i++) {
            float4 v = row[lane + 32 * i];
            float4 q = qm[lane + 32 * i];
            ss += v.x * v.x + v.y * v.y + v.z * v.z + v.w * v.w;
            dq += v.x * q.x + v.y * q.y + v.z * q.z + v.w * q.w;
        }
#pragma unroll
        for (int o = 16; o; o >>= 1) {
            ss += __shfl_xor_sync(0xffffffffu, ss, o);
            dq += __shfl_xor_sync(0xffffffffu, dq, o);
        }
        if (lane == 0) {
            g_inv_e[wid] = 1.0f / fmaxf(sqrtf(ss), 1.0f);
            g_cdot[wid]  = dq;
        }
    } else if (wid < MP1 + L) {
        int l = wid - MP1;
        const float4* row = (const float4*)(pos + (size_t)l * D);
        float ss = 0.0f;
#pragma unroll
        for (int i = 0; i < 4; i++) {
            float4 v = row[lane + 32 * i];
            ss += v.x * v.x + v.y * v.y + v.z * v.z + v.w * v.w;
        }
#pragma unroll
        for (int o = 16; o; o >>= 1) ss += __shfl_xor_sync(0xffffffffu, ss, o);
        if (lane == 0) g_inv_p[l] = 1.0f / fmaxf(sqrtf(ss), 1.0f);
    }
}

// ---------------------------------------------------------------------------
// K2: masked-row attention logits, all batches in one pass over pos_w, with
//     SOFTMAX FUSED via deferred normalization: |logit| <= 2/32, so exp is
//     numerically safe without max-shift. Writes e = exp(logit) to g_enum and
//     accumulates per-batch sums into g_sum via block-level reduction.
// ---------------------------------------------------------------------------
__global__ __launch_bounds__(256) void k_logits(const float* __restrict__ pos,
                                                const int* __restrict__ x,
                                                const int* __restrict__ mask_idx) {
    __shared__ float s_pw[B][D];   // 32 KB
    __shared__ int   s_pidx[B];
    __shared__ float s_pinv[B];
    __shared__ float s_esum[B];
    int tid = threadIdx.x;
    if (tid < B) {
        int p = mask_idx[tid];
        s_pidx[tid] = p;
        s_pinv[tid] = g_inv_p[p];
        s_esum[tid] = 0.0f;
    }
    __syncthreads();
    for (int i = tid; i < B * D; i += 256) {
        int b = i >> 9, d = i & (D - 1);
        s_pw[b][d] = pos[(size_t)s_pidx[b] * D + d];
    }
    __syncthreads();

    int w = tid >> 5, lane = tid & 31;
    int m = blockIdx.x * 8 + w;

    const float4* prow = (const float4*)(pos + (size_t)m * D);
    float4 v[4];
#pragma unroll
    for (int i = 0; i < 4; i++) v[i] = prow[lane + 32 * i];
    float invm  = g_inv_p[m];
    float inv_eM = g_inv_e[M];

    float c_l = 0.0f;
    if (lane < B) {
        int t = (m == s_pidx[lane]) ? M : x[lane * L + m];
        c_l = g_cdot[t] * g_inv_e[t];
    }

#pragma unroll
    for (int b = 0; b < B; b++) {
        const float4* sp = (const float4*)s_pw[b];
        float pd = 0.0f;
#pragma unroll
        for (int i = 0; i < 4; i++) {
            float4 u = sp[lane + 32 * i];
            pd += v[i].x * u.x + v[i].y * u.y + v[i].z * u.z + v[i].w * u.w;
        }
#pragma unroll
        for (int o = 16; o; o >>= 1) pd += __shfl_xor_sync(0xffffffffu, pd, o);
        float cb = __shfl_sync(0xffffffffu, c_l, b);
        if (lane == 0) {
            float e = expf((cb * inv_eM + pd * invm * s_pinv[b]) * (1.0f / 32.0f));
            g_enum[b * L + m] = e;
            atomicAdd(&s_esum[b], e);
        }
    }
    __syncthreads();
    if (tid < B) atomicAdd(&g_sum[tid], s_esum[tid]);
}

// ---------------------------------------------------------------------------
// K3: sel_output[b] = sum_m (e[b][m]/sum_b) * inv_e[t] * emb_w[t].
//     grid (L/64, B), block 512: 4 m-subgroups x 128 column-threads (the
//     measured-best selout: 12.6us @ occ 82%).
// ---------------------------------------------------------------------------
__global__ __launch_bounds__(512) void k_selout(const float* __restrict__ emb,
                                                const int* __restrict__ x,
                                                const int* __restrict__ mask_idx) {
    __shared__ float  s_p[64];
    __shared__ int    s_t[64];
    __shared__ float4 s_acc[3][128];   // partials from subgroups 1..3
    int b = blockIdx.y, m0 = blockIdx.x * 64;
    int p = mask_idx[b];
    if (threadIdx.x < 64) {
        float invs = 1.0f / g_sum[b];
        int m = m0 + threadIdx.x;
        int t = (m == p) ? M : x[b * L + m];
        s_t[threadIdx.x] = t;
        s_p[threadIdx.x] = g_enum[b * L + m] * invs * g_inv_e[t];
    }
    __syncthreads();

    const float4* emb4 = (const float4*)emb;
    int c = threadIdx.x & 127;     // float4 column 0..127
    int s = threadIdx.x >> 7;      // subgroup 0..3 -> rows s*16 .. s*16+15
    float4 acc = make_float4(0.f, 0.f, 0.f, 0.f);
#pragma unroll
    for (int i = 0; i < 16; i++) {
        int   r = s_t[s * 16 + i];
        float w = s_p[s * 16 + i];
        float4 v = emb4[(size_t)r * (D / 4) + c];
        acc.x += w * v.x; acc.y += w * v.y; acc.z += w * v.z; acc.w += w * v.w;
    }
    if (s > 0) s_acc[s - 1][c] = acc;
    __syncthreads();
    if (s == 0) {
        float4 a1 = s_acc[0][c], a2 = s_acc[1][c], a3 = s_acc[2][c];
        acc.x += a1.x + a2.x + a3.x;
        acc.y += a1.y + a2.y + a3.y;
        acc.z += a1.z + a2.z + a3.z;
        acc.w += a1.w + a2.w + a3.w;
        float* dst = g_sel + b * D + c * 4;
        atomicAdd(dst + 0, acc.x);
        atomicAdd(dst + 1, acc.y);
        atomicAdd(dst + 2, acc.z);
        atomicAdd(dst + 3, acc.w);
    }
}

// ---------------------------------------------------------------------------
// K4: inner_prod[b][j] = (sel[b] . emb_w[j]) * inv_e[j] for j < M.
//     Measured-best variant (R4 build, 90.6us total): grid M/8 = 4000 blocks,
//     256 threads, warp-per-j, emb row read once into registers, dotted
//     against all 16 batches from smem.
//     Block 0 additionally copies sel_output into out[1..B*D].
// ---------------------------------------------------------------------------
__global__ __launch_bounds__(256) void k_ip(const float* __restrict__ emb,
                                            float* __restrict__ out, int out_size) {
    __shared__ float s_sel[B * D];  // 32 KB
    for (int i = threadIdx.x; i < B * D; i += 256) s_sel[i] = g_sel[i];
    __syncthreads();

    if (blockIdx.x == 0) {
        int lim = out_size - 1; if (lim > B * D) lim = B * D;
        for (int i = threadIdx.x; i < lim; i += 256) out[1 + i] = s_sel[i];
    }

    int j    = blockIdx.x * 8 + (threadIdx.x >> 5);
    int lane = threadIdx.x & 31;
    const float4* row = (const float4*)(emb + (size_t)j * D);
    float4 v[4];
#pragma unroll
    for (int i = 0; i < 4; i++) v[i] = row[lane + 32 * i];
    float invj = g_inv_e[j];

#pragma unroll
    for (int b = 0; b < B; b++) {
        const float4* sb = (const float4*)(s_sel + b * D);
        float dsum = 0.0f;
#pragma unroll
        for (int i = 0; i < 4; i++) {
            float4 u = sb[lane + 32 * i];
            dsum += v[i].x * u.x + v[i].y * u.y + v[i].z * u.z + v[i].w * u.w;
        }
#pragma unroll
        for (int o = 16; o; o >>= 1) dsum += __shfl_xor_sync(0xffffffffu, dsum, o);
        if (lane == 0) g_ip[b * M + j] = dsum * invj;
    }
}

// ---------------------------------------------------------------------------
// K5: per-batch log-softmax over M and NLL into out[0]. NO max pass needed:
//     ip in [-1,1] (sel is a convex combination of <=1-norm rows), exp safe.
// ---------------------------------------------------------------------------
__global__ __launch_bounds__(1024) void k_loss(const int* __restrict__ x,
                                               const int* __restrict__ mask_idx,
                                               float* __restrict__ out) {
    __shared__ float sred[32];
    int b = blockIdx.x, tid = threadIdx.x, lane = tid & 31, w = tid >> 5;
    const float* ip = g_ip + b * M;

    float s = 0.0f;
    for (int i = tid; i < M; i += 1024) s += expf(ip[i]);
#pragma unroll
    for (int o = 16; o; o >>= 1) s += __shfl_xor_sync(0xffffffffu, s, o);
    if (lane == 0) sred[w] = s;
    __syncthreads();
    if (w == 0) {
        float s2 = sred[lane];
#pragma unroll
        for (int o = 16; o; o >>= 1) s2 += __shfl_xor_sync(0xffffffffu, s2, o);
        if (lane == 0) sred[0] = s2;
    }
    __syncthreads();
    if (tid == 0) {
        int t = x[b * L + mask_idx[b]];
        float logp = ip[t] - logf(sred[0]);
        atomicAdd(out, -logp * (1.0f / (float)B));
    }
}

// ---------------------------------------------------------------------------
extern "C" void kernel_launch(void* const* d_in, const int* in_sizes, int n_in,
                              void* d_out, int out_size) {
    const int*   x    = nullptr;
    const int*   midx = nullptr;
    const float* emb  = nullptr;
    const float* pos  = nullptr;
    for (int i = 0; i < n_in; i++) {
        switch (in_sizes[i]) {
            case B * L:     x    = (const int*)d_in[i];   break;
            case B:         midx = (const int*)d_in[i];   break;
            case MP1 * D:   emb  = (const float*)d_in[i]; break;
            case L * D:     pos  = (const float*)d_in[i]; break;
            default: break;
        }
    }
    float* out = (float*)d_out;

    // K1: norms + cdot + zero accumulators
    {
        int warps = MP1 + L;
        int blocks = (warps + 7) / 8;
        k_norms<<<blocks, 256>>>(emb, pos, out, out_size);
    }
    // K2: logits + fused exp + per-batch sums (softmax node eliminated)
    k_logits<<<L / 8, 256>>>(pos, x, midx);
    // K3: weighted gather sum -> sel_output
    {
        dim3 grid(L / 64, B);
        k_selout<<<grid, 512>>>(emb, x, midx);
    }
    // K4: inner products vs full vocab (measured-best variant)
    k_ip<<<M / 8, 256>>>(emb, out, out_size);
    // K5: log-softmax (no max pass) + loss -> out[0]
    k_loss<<<B, 1024>>>(x, midx, out);
}